// round 8
// baseline (speedup 1.0000x reference)
#include <cuda_runtime.h>
#include <cuda_fp16.h>
#include <cstdint>
#include <mma.h>

using namespace nvcuda;

#define CDIM   128
#define HEADS  4
#define HD     32
#define NTOK   49
#define NPAD   64
#define NWIN   64
#define NBLK   4096
#define NTHR   256

constexpr int KAUG = 144;   // 128 + 16 augmented K (bias fold)
constexpr int LDHA = 152;   // half stride, augmented tiles (304B rows)
constexpr int LDH  = 136;   // half stride, 128-wide tiles (272B rows)
constexpr int LDSf = 68;    // float stride, S tiles; P uses 136-half stride (same bytes)
constexpr int LDC  = 132;   // float stride, fp32 out staging

// ---- shared memory byte offsets (total 110592 B => 2 CTAs/SM) ----
constexpr int OFF_XA  = 0;        // 64x152 half  = 19456
constexpr int OFF_WA  = 19456;    // 128x152 half = 38912   (XA+WA = 58368, dead after projections)
constexpr int OFF_Q   = 58368;    // 64x136 half  = 17408
constexpr int OFF_K   = 75776;    // 64x136 half
constexpr int OFF_V   = 93184;    // 64x136 half  -> end 110592
// aliases:
constexpr int OFF_S   = 0;        // 2 heads x 64x68 f32 = 34816 (over XA+WA)
constexpr int OFF_CTX = 34816;    // 64x152 half = 19456 (over WA tail)   -> 54272 <= 58368
constexpr int OFF_WO  = 58368;    // 128x152 half = 38912 (over dead Q,K + V head) after attention
constexpr int OFF_C   = 0;        // 64x132 f32 = 33792 (over dead S)
constexpr int SMEM_BYTES = 110592;

// 49x128 fp32 window -> 64x152 half aug tile (aug col128=1 for real rows, pad rows all-zero)
__device__ __forceinline__ void load_x_aug(const float* __restrict__ src, __half* dst, int tid) {
    #pragma unroll
    for (int i = tid; i < (NPAD * CDIM) / 4; i += NTHR) {
        int r = (i * 4) >> 7, c = (i * 4) & 127;
        float4 v = (r < NTOK) ? reinterpret_cast<const float4*>(src)[i]
                              : make_float4(0.f, 0.f, 0.f, 0.f);
        __half2* d = reinterpret_cast<__half2*>(dst + r * LDHA + c);
        d[0] = __floats2half2_rn(v.x, v.y);
        d[1] = __floats2half2_rn(v.z, v.w);
    }
    if (tid < NPAD) {
        __half2* d = reinterpret_cast<__half2*>(dst + tid * LDHA + 128);
        d[0] = __floats2half2_rn(tid < NTOK ? 1.f : 0.f, 0.f);
        #pragma unroll
        for (int j = 1; j < 12; j++) d[j] = __floats2half2_rn(0.f, 0.f);
    }
}

// 128x128 fp32 weight + bias -> 128x152 half aug tile (col128 = bias[j])
__device__ __forceinline__ void load_w_aug(const float* __restrict__ W,
                                           const float* __restrict__ bias,
                                           __half* dst, int tid) {
    #pragma unroll
    for (int i = tid; i < (CDIM * CDIM) / 4; i += NTHR) {
        int r = (i * 4) >> 7, c = (i * 4) & 127;
        float4 v = reinterpret_cast<const float4*>(W)[i];
        __half2* d = reinterpret_cast<__half2*>(dst + r * LDHA + c);
        d[0] = __floats2half2_rn(v.x, v.y);
        d[1] = __floats2half2_rn(v.z, v.w);
    }
    if (tid < CDIM) {
        __half2* d = reinterpret_cast<__half2*>(dst + tid * LDHA + 128);
        d[0] = __floats2half2_rn(bias[tid], 0.f);
        #pragma unroll
        for (int j = 1; j < 12; j++) d[j] = __floats2half2_rn(0.f, 0.f);
    }
}

// C[64,128] = Aaug[64,144] @ Baug^T -> half dst; 8 warps as 2m x 4n, each 32x32
__device__ __forceinline__ void gemm_proj_h(const __half* sA, const __half* sB,
                                            __half* dst, int warp) {
    const int wm = (warp & 1) * 32;
    const int wn = (warp >> 1) * 32;

    wmma::fragment<wmma::accumulator, 16, 16, 16, float> acc[2][2];
    #pragma unroll
    for (int mi = 0; mi < 2; mi++)
        #pragma unroll
        for (int ni = 0; ni < 2; ni++) wmma::fill_fragment(acc[mi][ni], 0.f);

    #pragma unroll
    for (int kk = 0; kk < KAUG; kk += 16) {
        wmma::fragment<wmma::matrix_a, 16, 16, 16, __half, wmma::row_major> a[2];
        wmma::fragment<wmma::matrix_b, 16, 16, 16, __half, wmma::col_major> b[2];
        #pragma unroll
        for (int mi = 0; mi < 2; mi++)
            wmma::load_matrix_sync(a[mi], sA + (wm + mi * 16) * LDHA + kk, LDHA);
        #pragma unroll
        for (int ni = 0; ni < 2; ni++) {
            wmma::load_matrix_sync(b[ni], sB + (wn + ni * 16) * LDHA + kk, LDHA);
            #pragma unroll
            for (int mi = 0; mi < 2; mi++)
                wmma::mma_sync(acc[mi][ni], a[mi], b[ni], acc[mi][ni]);
        }
    }
    #pragma unroll
    for (int mi = 0; mi < 2; mi++)
        #pragma unroll
        for (int ni = 0; ni < 2; ni++) {
            wmma::fragment<wmma::accumulator, 16, 16, 16, __half> hacc;
            #pragma unroll
            for (int t = 0; t < hacc.num_elements; t++)
                hacc.x[t] = __float2half_rn(acc[mi][ni].x[t]);
            wmma::store_matrix_sync(dst + (wm + mi * 16) * LDH + wn + ni * 16,
                                    hacc, LDH, wmma::mem_row_major);
        }
}

__global__ void __launch_bounds__(NTHR, 2)
fused_wmca_kernel(const float* __restrict__ q_in, const float* __restrict__ k_in,
                  const float* __restrict__ v_in, const float* __restrict__ mask,
                  const float* __restrict__ Wq, const float* __restrict__ bq,
                  const float* __restrict__ Wk, const float* __restrict__ bk,
                  const float* __restrict__ Wv, const float* __restrict__ bv,
                  const float* __restrict__ Wo, const float* __restrict__ bo,
                  const float* __restrict__ rpb, const int* __restrict__ relidx,
                  float* __restrict__ out) {
    extern __shared__ char smraw[];
    __half* sXA  = reinterpret_cast<__half*>(smraw + OFF_XA);
    __half* sWA  = reinterpret_cast<__half*>(smraw + OFF_WA);
    __half* sQh  = reinterpret_cast<__half*>(smraw + OFF_Q);
    __half* sKh  = reinterpret_cast<__half*>(smraw + OFF_K);
    __half* sVh  = reinterpret_cast<__half*>(smraw + OFF_V);
    __half* sCtx = reinterpret_cast<__half*>(smraw + OFF_CTX);
    __half* sWO  = reinterpret_cast<__half*>(smraw + OFF_WO);
    float*  sS   = reinterpret_cast<float*>(smraw + OFF_S);
    __half* sP   = reinterpret_cast<__half*>(smraw + OFF_S);   // P in place over S
    float*  sC   = reinterpret_cast<float*>(smraw + OFF_C);

    const int tid = threadIdx.x;
    const int warp = tid >> 5;
    const int w = blockIdx.x;
    const long base = (long)w * NTOK * CDIM;

    // ---------------- Q projection (bias folded) ----------------
    load_x_aug(q_in + base, sXA, tid);
    load_w_aug(Wq, bq, sWA, tid);
    __syncthreads();
    gemm_proj_h(sXA, sWA, sQh, warp);
    __syncthreads();

    // ---------------- K projection ----------------
    load_x_aug(k_in + base, sXA, tid);
    load_w_aug(Wk, bk, sWA, tid);
    __syncthreads();
    gemm_proj_h(sXA, sWA, sKh, warp);
    __syncthreads();

    // ---------------- V projection ----------------
    load_x_aug(v_in + base, sXA, tid);
    load_w_aug(Wv, bv, sWA, tid);
    __syncthreads();
    gemm_proj_h(sXA, sWA, sVh, warp);
    __syncthreads();
    // XA + WA dead -> S / ctx region. Init ctx aug columns once.
    if (tid < NPAD) {
        __half2* d = reinterpret_cast<__half2*>(sCtx + tid * LDHA + 128);
        d[0] = __floats2half2_rn(tid < NTOK ? 1.f : 0.f, 0.f);
        #pragma unroll
        for (int j = 1; j < 12; j++) d[j] = __floats2half2_rn(0.f, 0.f);
    }

    // ---------------- attention: two head-pair passes ----------------
    #pragma unroll 1
    for (int hp = 0; hp < 2; hp++) {
        const int hl = warp >> 2;              // head-local 0/1
        const int head = hp * 2 + hl;
        const int mo = (warp & 3) * 16;

        // S = Q @ K^T  (per head: 4 warps x 16 rows x 64 cols)
        {
            wmma::fragment<wmma::accumulator, 16, 16, 16, float> acc[4];
            #pragma unroll
            for (int ni = 0; ni < 4; ni++) wmma::fill_fragment(acc[ni], 0.f);

            #pragma unroll
            for (int kk = 0; kk < HD; kk += 16) {
                wmma::fragment<wmma::matrix_a, 16, 16, 16, __half, wmma::row_major> a;
                wmma::fragment<wmma::matrix_b, 16, 16, 16, __half, wmma::col_major> b[4];
                wmma::load_matrix_sync(a, sQh + mo * LDH + head * HD + kk, LDH);
                #pragma unroll
                for (int ni = 0; ni < 4; ni++) {
                    wmma::load_matrix_sync(b[ni], sKh + (ni * 16) * LDH + head * HD + kk, LDH);
                    wmma::mma_sync(acc[ni], a, b[ni], acc[ni]);
                }
            }
            __syncthreads();   // pass>=1: prior AV done reading P before overwriting S
            #pragma unroll
            for (int ni = 0; ni < 4; ni++)
                wmma::store_matrix_sync(sS + hl * NPAD * LDSf + mo * LDSf + ni * 16,
                                        acc[ni], LDSf, wmma::mem_row_major);
        }
        __syncthreads();

        // softmax: fp32 S row -> half P row, in place (pad rows are exact zeros)
        if (tid < 2 * NTOK) {
            const int hhl = tid / NTOK, i = tid % NTOK;
            const int hh = hp * 2 + hhl;
            const float* row = sS + hhl * NPAD * LDSf + i * LDSf;
            __half* prow = sP + hhl * NPAD * LDH + i * LDH;
            const float* mrow = mask + (long)(w & (NWIN - 1)) * NTOK * NTOK + i * NTOK;
            const int* rrow = relidx + i * NTOK;
            const float scale = 0.17677669529663687f;  // 32^-0.5
            float sv[NTOK];
            float mx = -1e30f;
            #pragma unroll 7
            for (int j = 0; j < NTOK; j++) {
                float s = row[j] * scale + __ldg(&rpb[rrow[j] * HEADS + hh]) + mrow[j];
                sv[j] = s;
                mx = fmaxf(mx, s);
            }
            float sum = 0.f;
            #pragma unroll 7
            for (int j = 0; j < NTOK; j++) { float e = __expf(sv[j] - mx); sv[j] = e; sum += e; }
            float inv = 1.f / sum;
            #pragma unroll 7
            for (int j = 0; j < NTOK; j++) prow[j] = __float2half_rn(sv[j] * inv);
            #pragma unroll
            for (int j = NTOK; j < NPAD; j++) prow[j] = __float2half_rn(0.f);
        }
        __syncthreads();

        // ctx = P @ V  (per head: 4 warps x 16 rows x 32 cols) -> ctx cols head*32
        {
            wmma::fragment<wmma::accumulator, 16, 16, 16, float> acc[2];
            #pragma unroll
            for (int ni = 0; ni < 2; ni++) wmma::fill_fragment(acc[ni], 0.f);

            #pragma unroll
            for (int kk = 0; kk < NPAD; kk += 16) {
                wmma::fragment<wmma::matrix_a, 16, 16, 16, __half, wmma::row_major> a;
                wmma::fragment<wmma::matrix_b, 16, 16, 16, __half, wmma::row_major> b[2];
                wmma::load_matrix_sync(a, sP + hl * NPAD * LDH + mo * LDH + kk, LDH);
                #pragma unroll
                for (int ni = 0; ni < 2; ni++) {
                    wmma::load_matrix_sync(b[ni], sVh + kk * LDH + head * HD + ni * 16, LDH);
                    wmma::mma_sync(acc[ni], a, b[ni], acc[ni]);
                }
            }
            #pragma unroll
            for (int ni = 0; ni < 2; ni++) {
                wmma::fragment<wmma::accumulator, 16, 16, 16, __half> hacc;
                #pragma unroll
                for (int t = 0; t < hacc.num_elements; t++)
                    hacc.x[t] = __float2half_rn(acc[ni].x[t]);
                wmma::store_matrix_sync(sCtx + mo * LDHA + head * HD + ni * 16,
                                        hacc, LDHA, wmma::mem_row_major);
            }
        }
        __syncthreads();
    }

    // ---------------- output projection: Y = ctx_aug @ WoAug^T ----------------
    load_w_aug(Wo, bo, sWO, tid);   // over dead Q/K/V regions
    __syncthreads();
    {
        const int wm = (warp & 1) * 32;
        const int wn = (warp >> 1) * 32;
        wmma::fragment<wmma::accumulator, 16, 16, 16, float> acc[2][2];
        #pragma unroll
        for (int mi = 0; mi < 2; mi++)
            #pragma unroll
            for (int ni = 0; ni < 2; ni++) wmma::fill_fragment(acc[mi][ni], 0.f);

        #pragma unroll
        for (int kk = 0; kk < KAUG; kk += 16) {
            wmma::fragment<wmma::matrix_a, 16, 16, 16, __half, wmma::row_major> a[2];
            wmma::fragment<wmma::matrix_b, 16, 16, 16, __half, wmma::col_major> b[2];
            #pragma unroll
            for (int mi = 0; mi < 2; mi++)
                wmma::load_matrix_sync(a[mi], sCtx + (wm + mi * 16) * LDHA + kk, LDHA);
            #pragma unroll
            for (int ni = 0; ni < 2; ni++) {
                wmma::load_matrix_sync(b[ni], sWO + (wn + ni * 16) * LDHA + kk, LDHA);
                #pragma unroll
                for (int mi = 0; mi < 2; mi++)
                    wmma::mma_sync(acc[mi][ni], a[mi], b[ni], acc[mi][ni]);
            }
        }
        __syncthreads();   // S region fully dead (P reads done) before sC overwrites it
        #pragma unroll
        for (int mi = 0; mi < 2; mi++)
            #pragma unroll
            for (int ni = 0; ni < 2; ni++)
                wmma::store_matrix_sync(sC + (wm + mi * 16) * LDC + wn + ni * 16,
                                        acc[mi][ni], LDC, wmma::mem_row_major);
    }
    __syncthreads();

    #pragma unroll
    for (int i = tid; i < (NTOK * CDIM) / 4; i += NTHR) {
        int r = (i * 4) >> 7, c = (i * 4) & 127;
        reinterpret_cast<float4*>(out + base)[i] =
            *reinterpret_cast<float4*>(&sC[r * LDC + c]);
    }
}

// ============================================================================
// launch
// ============================================================================
extern "C" void kernel_launch(void* const* d_in, const int* in_sizes, int n_in,
                              void* d_out, int out_size) {
    const float* q    = (const float*)d_in[0];
    const float* k    = (const float*)d_in[1];
    const float* v    = (const float*)d_in[2];
    const float* mask = (const float*)d_in[3];
    const float* Wq   = (const float*)d_in[4];
    const float* bq   = (const float*)d_in[5];
    const float* Wk   = (const float*)d_in[6];
    const float* bk   = (const float*)d_in[7];
    const float* Wv   = (const float*)d_in[8];
    const float* bv   = (const float*)d_in[9];
    const float* Wo   = (const float*)d_in[10];
    const float* bo   = (const float*)d_in[11];
    const float* rpb  = (const float*)d_in[12];
    const int*   ridx = (const int*)d_in[13];
    float* out = (float*)d_out;

    cudaFuncSetAttribute(fused_wmca_kernel, cudaFuncAttributeMaxDynamicSharedMemorySize,
                         SMEM_BYTES);

    fused_wmca_kernel<<<NBLK, NTHR, SMEM_BYTES>>>(q, k, v, mask, Wq, bq, Wk, bk, Wv, bv,
                                                  Wo, bo, rpb, ridx, out);
}